// round 2
// baseline (speedup 1.0000x reference)
#include <cuda_runtime.h>

// ---------------- scratch (device globals; no allocations allowed) ----------
__device__ float g_pool1[32 * 64 * 64 * 32];     // conv1+pool output (16.8M floats)
__device__ float g_conv2[32 * 64 * 64 * 64];     // conv2+relu output (8.39M floats)
__device__ int   g_amax[32 * 64];                // per (b,c) spatial argmax index
__device__ float g_csum[32 * 64];                // per (b,c) spatial sum (per_sample)
__device__ float g_part[64 * 32 * 1024];         // dense1 split-K partials
__device__ float g_hidden[32 * 1024];            // dense1 output (post relu)

// ---------------- K1: conv1 (3x3x1->32, SAME) + relu + 2x2 maxpool ----------
__global__ void k_conv1_pool(const float* __restrict__ in,
                             const float* __restrict__ w,
                             const float* __restrict__ bias) {
    int idx = blockIdx.x * 256 + threadIdx.x;     // 32*64*64*32 = 4,194,304
    int c = idx & 31;
    int x = (idx >> 5) & 63;
    int y = (idx >> 11) & 63;
    int b = idx >> 17;

    float wr[9];
#pragma unroll
    for (int i = 0; i < 9; i++) wr[i] = w[i * 32 + c];
    float bc = bias[c];
    const float* ib = in + b * 16384;

    float m = 0.f;   // relu(conv) >= 0, so pool-of-relu == max(0, conv taps)
#pragma unroll
    for (int sy = 0; sy < 2; sy++) {
#pragma unroll
        for (int sx = 0; sx < 2; sx++) {
            int oy = 2 * y + sy, ox = 2 * x + sx;
            float a = bc;
#pragma unroll
            for (int ky = 0; ky < 3; ky++) {
                int yy = oy + ky - 1;
                if ((unsigned)yy < 128u) {
#pragma unroll
                    for (int kx = 0; kx < 3; kx++) {
                        int xx = ox + kx - 1;
                        if ((unsigned)xx < 128u)
                            a = fmaf(ib[yy * 128 + xx], wr[ky * 3 + kx], a);
                    }
                }
            }
            m = fmaxf(m, a);
        }
    }
    g_pool1[idx] = m;
}

// ---------------- K2: conv2 (3x3x32->64, SAME) + relu -----------------------
__global__ void k_conv2(const float* __restrict__ w,
                        const float* __restrict__ bias) {
    int idx = blockIdx.x * 256 + threadIdx.x;     // 32*64*64*64 = 8,388,608
    int c = idx & 63;
    int x = (idx >> 6) & 63;
    int y = (idx >> 12) & 63;
    int b = idx >> 18;

    float acc = bias[c];
#pragma unroll
    for (int ky = 0; ky < 3; ky++) {
        int yy = y + ky - 1;
        if ((unsigned)yy >= 64u) continue;
#pragma unroll
        for (int kx = 0; kx < 3; kx++) {
            int xx = x + kx - 1;
            if ((unsigned)xx >= 64u) continue;
            const float4* ip = (const float4*)(g_pool1 + ((b * 64 + yy) * 64 + xx) * 32);
            const float* wp = w + (ky * 3 + kx) * 2048 + c;   // (tap*32+ci)*64 + c
#pragma unroll
            for (int q = 0; q < 8; q++) {
                float4 v = ip[q];
                acc = fmaf(v.x, wp[(4 * q + 0) * 64], acc);
                acc = fmaf(v.y, wp[(4 * q + 1) * 64], acc);
                acc = fmaf(v.z, wp[(4 * q + 2) * 64], acc);
                acc = fmaf(v.w, wp[(4 * q + 3) * 64], acc);
            }
        }
    }
    g_conv2[idx] = fmaxf(acc, 0.f);
}

// ---------------- K3: per-(b,c) spatial argmax + spatial sum -----------------
__global__ void k_amax(void) {
    int b = blockIdx.x;
    int c = threadIdx.x & 63;
    int tg = threadIdx.x >> 6;    // 0..7
    const float* base = g_conv2 + b * (4096 * 64);
    float best = -1e30f;
    int bi = 0;
    float s = 0.f;
    int p0 = tg * 512;
    for (int p = p0; p < p0 + 512; p++) {
        float v = base[p * 64 + c];
        s += v;
        if (v > best) { best = v; bi = p; }   // strict > keeps first index
    }
    __shared__ float sb[8][64];
    __shared__ int   si[8][64];
    __shared__ float ss[8][64];
    sb[tg][c] = best; si[tg][c] = bi; ss[tg][c] = s;
    __syncthreads();
    if (tg == 0) {
        float B = sb[0][c]; int I = si[0][c]; float S = ss[0][c];
#pragma unroll
        for (int g = 1; g < 8; g++) {
            S += ss[g][c];
            if (sb[g][c] > B) { B = sb[g][c]; I = si[g][c]; }  // earlier group wins ties
        }
        g_amax[b * 64 + c] = I;
        g_csum[b * 64 + c] = S;
    }
}

// ---------------- K4: mask * conv2, relu, 2x2 maxpool -> d_out pool region ---
__global__ void k_maskpool(float* __restrict__ outp) {
    int idx = blockIdx.x * 256 + threadIdx.x;   // 32*32*32*64 = 2,097,152
    int c = idx & 63;
    int px = (idx >> 6) & 31;
    int py = (idx >> 11) & 31;
    int b = idx >> 16;

    int am = g_amax[b * 64 + c];
    float mux = (float)(am >> 6) * (1.f / 31.5f) - 1.f;   // row coord
    float muy = (float)(am & 63) * (1.f / 31.5f) - 1.f;   // col coord

    float m = 0.f;   // relu(masked) >= 0
#pragma unroll
    for (int sy = 0; sy < 2; sy++) {
#pragma unroll
        for (int sx = 0; sx < 2; sx++) {
            int yy = 2 * py + sy, xx = 2 * px + sx;
            float ly = (float)yy * (2.f / 63.f) - 1.f;
            float lx = (float)xx * (2.f / 63.f) - 1.f;
            float mask = 1.f - 0.5f * (fabsf(ly - mux) + fabsf(lx - muy));
            mask = fmaxf(mask, -1.f);
            float v = g_conv2[((b * 64 + yy) * 64 + xx) * 64 + c] * mask;
            m = fmaxf(m, v);
        }
    }
    outp[idx] = m;
}

// ---------------- K5: segment-mean over labels -> argmax category per filter -
// Labels dtype is ambiguous (reference asks for int64; JAX default config
// yields int32). Detect on-device from the first 128 bytes only: an int64
// buffer with values 0..9 has every odd 32-bit word == 0. Only after deciding
// int64 do we touch bytes 128..255 (in-bounds in that case).
// numpy argmax semantics: first NaN (empty category -> 0/0) beats everything.
__global__ void k_filters(const int* __restrict__ lab32,
                          float* __restrict__ outf) {
    __shared__ int lbl[32];
    if (threadIdx.x == 0) {
        bool is64 = true;
        for (int i = 1; i < 32; i += 2)
            if (lab32[i] != 0) { is64 = false; break; }
        if (is64) {
            const long long* l64 = (const long long*)lab32;
            for (int b = 0; b < 32; b++) lbl[b] = (int)l64[b];
        } else {
            for (int b = 0; b < 32; b++) lbl[b] = lab32[b];
        }
    }
    __syncthreads();

    int c = threadIdx.x;   // 64 threads
    float sums[10];
    int cnt[10];
#pragma unroll
    for (int i = 0; i < 10; i++) { sums[i] = 0.f; cnt[i] = 0; }
    for (int b = 0; b < 32; b++) {
        int l = lbl[b];
        sums[l] += g_csum[b * 64 + c];
        cnt[l]++;
    }
    float best = 0.f;
    int bi = 0;
    bool have = false, bnan = false;
    for (int cat = 0; cat < 10; cat++) {
        float v = sums[cat] / (float)cnt[cat];    // cnt==0 -> 0/0 = NaN
        bool vn = isnan(v);
        if (!bnan && (vn || !have || v > best)) {
            best = v; bi = cat; bnan = vn; have = true;
        }
    }
    outf[c] = (float)bi;
}

// ---------------- K6: dense1 split-K partials --------------------------------
__global__ void k_dense1(const float* __restrict__ x,
                         const float* __restrict__ w) {
    int n = blockIdx.x * 128 + threadIdx.x;
    int k0 = blockIdx.y * 1024;
    float acc[32];
#pragma unroll
    for (int b = 0; b < 32; b++) acc[b] = 0.f;
    __shared__ float xs[32 * 128];

    for (int kt = 0; kt < 1024; kt += 128) {
        __syncthreads();
        for (int i = threadIdx.x; i < 4096; i += 128) {
            int b = i >> 7, kk = i & 127;
            xs[i] = x[b * 65536 + k0 + kt + kk];
        }
        __syncthreads();
#pragma unroll 4
        for (int kk = 0; kk < 128; kk++) {
            float wv = w[(k0 + kt + kk) * 1024 + n];
#pragma unroll
            for (int b = 0; b < 32; b++)
                acc[b] = fmaf(xs[b * 128 + kk], wv, acc[b]);
        }
    }
    float* p = g_part + (blockIdx.y * 32) * 1024 + n;
#pragma unroll
    for (int b = 0; b < 32; b++) p[b * 1024] = acc[b];
}

// ---------------- K7: reduce partials + bias + relu --------------------------
__global__ void k_dense1_fin(const float* __restrict__ bias) {
    int idx = blockIdx.x * 256 + threadIdx.x;   // 32*1024
    int n = idx & 1023, b = idx >> 10;
    float s = 0.f;
#pragma unroll 8
    for (int ks = 0; ks < 64; ks++) s += g_part[(ks * 32 + b) * 1024 + n];
    g_hidden[idx] = fmaxf(s + bias[n], 0.f);
}

// ---------------- K8: dense2 -> logits ---------------------------------------
__global__ void k_dense2(const float* __restrict__ w,
                         const float* __restrict__ bias,
                         float* __restrict__ logits) {
    int t = threadIdx.x;
    if (t >= 320) return;
    int b = t / 10, j = t % 10;
    float s = bias[j];
    const float* h = g_hidden + b * 1024;
#pragma unroll 8
    for (int k = 0; k < 1024; k++)
        s = fmaf(h[k], w[k * 10 + j], s);
    logits[b * 10 + j] = s;
}

// ---------------- launcher ---------------------------------------------------
extern "C" void kernel_launch(void* const* d_in, const int* in_sizes, int n_in,
                              void* d_out, int out_size) {
    const float* inputs = (const float*)d_in[0];
    const int*   labels = (const int*)d_in[1];   // dtype resolved on-device
    const float* c1w = (const float*)d_in[2];
    const float* c1b = (const float*)d_in[3];
    const float* c2w = (const float*)d_in[4];
    const float* c2b = (const float*)d_in[5];
    const float* d1w = (const float*)d_in[6];
    const float* d1b = (const float*)d_in[7];
    const float* d2w = (const float*)d_in[8];
    const float* d2b = (const float*)d_in[9];

    float* out = (float*)d_out;
    float* out_logits = out;                       // (32,10)   = 320
    float* out_pool   = out + 320;                 // (32,32,32,64) = 2,097,152
    float* out_filt   = out + 320 + 2097152;       // (64,)

    k_conv1_pool<<<16384, 256>>>(inputs, c1w, c1b);
    k_conv2<<<32768, 256>>>(c2w, c2b);
    k_amax<<<32, 512>>>();
    k_maskpool<<<8192, 256>>>(out_pool);
    k_filters<<<1, 64>>>(labels, out_filt);
    k_dense1<<<dim3(8, 64), 128>>>(out_pool, d1w);
    k_dense1_fin<<<128, 256>>>(d1b);
    k_dense2<<<1, 320>>>(d2w, d2b, out_logits);
}

// round 3
// speedup vs baseline: 2.1069x; 2.1069x over previous
#include <cuda_runtime.h>

typedef unsigned long long ull_t;

// packed fp32x2 FMA (sm_100+): two independent fp32 FMAs, bit-exact vs scalar
__device__ __forceinline__ float2 ffma2(float2 a, float2 b, float2 c) {
    float2 d;
    asm("fma.rn.f32x2 %0, %1, %2, %3;"
        : "=l"(reinterpret_cast<ull_t&>(d))
        : "l"(reinterpret_cast<ull_t&>(a)),
          "l"(reinterpret_cast<ull_t&>(b)),
          "l"(reinterpret_cast<ull_t&>(c)));
    return d;
}

// ---------------- scratch (device globals; no allocations allowed) ----------
__device__ float g_pool1[32 * 64 * 64 * 32];     // conv1+pool output
__device__ float g_conv2[32 * 64 * 64 * 64];     // conv2+relu output
__device__ int   g_amax[32 * 64];                // per (b,c) spatial argmax
__device__ float g_csum[32 * 64];                // per (b,c) spatial sum
__device__ float g_part[128 * 32 * 1024];        // dense1 split-K partials
__device__ float g_hidden[32 * 1024];            // dense1 output (post relu)

// ---------------- K1: conv1 (3x3x1->32, SAME) + relu + 2x2 maxpool ----------
__global__ void k_conv1_pool(const float* __restrict__ in,
                             const float* __restrict__ w,
                             const float* __restrict__ bias) {
    int idx = blockIdx.x * 256 + threadIdx.x;     // 32*64*64*32
    int c = idx & 31;
    int x = (idx >> 5) & 63;
    int y = (idx >> 11) & 63;
    int b = idx >> 17;

    float wr[9];
#pragma unroll
    for (int i = 0; i < 9; i++) wr[i] = w[i * 32 + c];
    float bc = bias[c];
    const float* ib = in + b * 16384;

    float m = 0.f;
#pragma unroll
    for (int sy = 0; sy < 2; sy++) {
#pragma unroll
        for (int sx = 0; sx < 2; sx++) {
            int oy = 2 * y + sy, ox = 2 * x + sx;
            float a = bc;
#pragma unroll
            for (int ky = 0; ky < 3; ky++) {
                int yy = oy + ky - 1;
                if ((unsigned)yy < 128u) {
#pragma unroll
                    for (int kx = 0; kx < 3; kx++) {
                        int xx = ox + kx - 1;
                        if ((unsigned)xx < 128u)
                            a = fmaf(ib[yy * 128 + xx], wr[ky * 3 + kx], a);
                    }
                }
            }
            m = fmaxf(m, a);
        }
    }
    g_pool1[idx] = m;
}

// ---------------- K2: conv2 (3x3x32->64, SAME) + relu, smem-tiled + FFMA2 ----
// Block: batch b, 16x16 spatial tile, all 64 output channels.
// Thread: 8 pixels (half row) x 8 channels (as 4 f32x2 pairs).
// smem: input tile [32ci][18y][20x-pad] (stride 370/ci for LDS.64 parity +
// conflict control) + weights [9][32][64].
#define IN_S_CI 370
#define CONV2_SMEM ((32 * IN_S_CI + 9 * 32 * 64) * 4)
__global__ void __launch_bounds__(256, 1) k_conv2(const float* __restrict__ w,
                                                  const float* __restrict__ bias) {
    extern __shared__ float sm[];
    float* in_s = sm;                 // [32][370]
    float* w_s  = sm + 32 * IN_S_CI;  // [9][32][64]

    int b  = blockIdx.x >> 4;
    int t  = blockIdx.x & 15;
    int ty = t >> 2, tx = t & 3;
    int tid = threadIdx.x;

    // input tile with halo (zero-pad SAME borders); coalesced on ci
    for (int i = tid; i < 32 * 18 * 18; i += 256) {
        int ci = i & 31;
        int rest = i >> 5;
        int sy = rest / 18, sx = rest - sy * 18;
        int gy = ty * 16 + sy - 1, gx = tx * 16 + sx - 1;
        float v = 0.f;
        if ((unsigned)gy < 64u && (unsigned)gx < 64u)
            v = g_pool1[((b * 64 + gy) * 64 + gx) * 32 + ci];
        in_s[ci * IN_S_CI + sy * 20 + sx] = v;
    }
    for (int i = tid; i < 9 * 32 * 64; i += 256)
        w_s[i] = w[i];
    __syncthreads();

    int cg = tid & 7;          // co = cg*8 + [0..8)
    int pg = tid >> 3;         // 0..31
    int r  = pg >> 1;          // tile row 0..15
    int x0 = (pg & 1) * 8;     // half-row start

    float2 acc[8][4];
    {
        const float2* bp = (const float2*)(bias + cg * 8);
#pragma unroll
        for (int jj = 0; jj < 4; jj++) {
            float2 bv = bp[jj];
#pragma unroll
            for (int j = 0; j < 8; j++) acc[j][jj] = bv;
        }
    }

#pragma unroll 1
    for (int tap = 0; tap < 9; tap++) {
        int ky = tap / 3, kx = tap - ky * 3;
        const float* ib = in_s + (r + ky) * 20 + (x0 + kx);
        const float* wb = w_s + tap * 2048 + cg * 8;
#pragma unroll 8
        for (int ci = 0; ci < 32; ci++) {
            const float*  ip = ib + ci * IN_S_CI;
            const float2* wp = (const float2*)(wb + ci * 64);
            float2 wv0 = wp[0], wv1 = wp[1], wv2 = wp[2], wv3 = wp[3];
#pragma unroll
            for (int j = 0; j < 8; j++) {
                float iv = ip[j];
                float2 a; a.x = iv; a.y = iv;
                acc[j][0] = ffma2(a, wv0, acc[j][0]);
                acc[j][1] = ffma2(a, wv1, acc[j][1]);
                acc[j][2] = ffma2(a, wv2, acc[j][2]);
                acc[j][3] = ffma2(a, wv3, acc[j][3]);
            }
        }
    }

    int gy  = ty * 16 + r;
    int gxb = tx * 16 + x0;
#pragma unroll
    for (int j = 0; j < 8; j++) {
        float2* op = (float2*)(g_conv2 + ((b * 64 + gy) * 64 + gxb + j) * 64 + cg * 8);
#pragma unroll
        for (int jj = 0; jj < 4; jj++) {
            float2 v = acc[j][jj];
            v.x = fmaxf(v.x, 0.f);
            v.y = fmaxf(v.y, 0.f);
            op[jj] = v;
        }
    }
}

// ---------------- K3: per-(b,c) spatial argmax + spatial sum -----------------
__global__ void k_amax(void) {
    int b = blockIdx.x;
    int c = threadIdx.x & 63;
    int tg = threadIdx.x >> 6;    // 0..7
    const float* base = g_conv2 + b * (4096 * 64);
    float best = -1e30f;
    int bi = 0;
    float s = 0.f;
    int p0 = tg * 512;
    for (int p = p0; p < p0 + 512; p++) {
        float v = base[p * 64 + c];
        s += v;
        if (v > best) { best = v; bi = p; }   // strict > keeps first index
    }
    __shared__ float sb[8][64];
    __shared__ int   si[8][64];
    __shared__ float ss[8][64];
    sb[tg][c] = best; si[tg][c] = bi; ss[tg][c] = s;
    __syncthreads();
    if (tg == 0) {
        float B = sb[0][c]; int I = si[0][c]; float S = ss[0][c];
#pragma unroll
        for (int g = 1; g < 8; g++) {
            S += ss[g][c];
            if (sb[g][c] > B) { B = sb[g][c]; I = si[g][c]; }
        }
        g_amax[b * 64 + c] = I;
        g_csum[b * 64 + c] = S;
    }
}

// ---------------- K4: mask * conv2, relu, 2x2 maxpool -> d_out pool region ---
__global__ void k_maskpool(float* __restrict__ outp) {
    int idx = blockIdx.x * 256 + threadIdx.x;   // 32*32*32*64
    int c = idx & 63;
    int px = (idx >> 6) & 31;
    int py = (idx >> 11) & 31;
    int b = idx >> 16;

    int am = g_amax[b * 64 + c];
    float mux = (float)(am >> 6) * (1.f / 31.5f) - 1.f;
    float muy = (float)(am & 63) * (1.f / 31.5f) - 1.f;

    float m = 0.f;
#pragma unroll
    for (int sy = 0; sy < 2; sy++) {
#pragma unroll
        for (int sx = 0; sx < 2; sx++) {
            int yy = 2 * py + sy, xx = 2 * px + sx;
            float ly = (float)yy * (2.f / 63.f) - 1.f;
            float lx = (float)xx * (2.f / 63.f) - 1.f;
            float mask = 1.f - 0.5f * (fabsf(ly - mux) + fabsf(lx - muy));
            mask = fmaxf(mask, -1.f);
            float v = g_conv2[((b * 64 + yy) * 64 + xx) * 64 + c] * mask;
            m = fmaxf(m, v);
        }
    }
    outp[idx] = m;
}

// ---------------- K5: segment-mean -> argmax category per filter -------------
__global__ void k_filters(const int* __restrict__ lab32,
                          float* __restrict__ outf) {
    __shared__ int lbl[32];
    if (threadIdx.x == 0) {
        bool is64 = true;
        for (int i = 1; i < 32; i += 2)
            if (lab32[i] != 0) { is64 = false; break; }
        if (is64) {
            const long long* l64 = (const long long*)lab32;
            for (int b = 0; b < 32; b++) lbl[b] = (int)l64[b];
        } else {
            for (int b = 0; b < 32; b++) lbl[b] = lab32[b];
        }
    }
    __syncthreads();

    int c = threadIdx.x;   // 64 threads
    float sums[10];
    int cnt[10];
#pragma unroll
    for (int i = 0; i < 10; i++) { sums[i] = 0.f; cnt[i] = 0; }
    for (int b = 0; b < 32; b++) {
        int l = lbl[b];
        sums[l] += g_csum[b * 64 + c];
        cnt[l]++;
    }
    float best = 0.f;
    int bi = 0;
    bool have = false, bnan = false;
    for (int cat = 0; cat < 10; cat++) {
        float v = sums[cat] / (float)cnt[cat];    // cnt==0 -> NaN wins (numpy)
        bool vn = isnan(v);
        if (!bnan && (vn || !have || v > best)) {
            best = v; bi = cat; bnan = vn; have = true;
        }
    }
    outf[c] = (float)bi;
}

// ---------------- K6: dense1 split-K with FFMA2 ------------------------------
// M=32, N=1024, K=65536. grid (2 n-halves, 128 k-splits), 256 threads.
// Thread: 2 adjacent n-cols x 32 batches (16 batch-pairs as f32x2).
// Per k: 1 LDG.64 (w pair) + 16 broadcast LDS.64 (x batch-pairs) + 32 FFMA2.
__global__ void __launch_bounds__(256, 2) k_dense1(const float* __restrict__ x,
                                                   const float* __restrict__ w) {
    __shared__ float xs[128 * 34];   // [kk][b] transposed, pad 34
    int tid = threadIdx.x;
    int n0 = blockIdx.x * 512 + tid * 2;
    int kbase = blockIdx.y * 512;

    float2 a0[16], a1[16];
#pragma unroll
    for (int i = 0; i < 16; i++) {
        a0[i] = make_float2(0.f, 0.f);
        a1[i] = make_float2(0.f, 0.f);
    }

    for (int t = 0; t < 512; t += 128) {
        __syncthreads();
        for (int i = tid; i < 4096; i += 256) {
            int kk = i & 127, bb = i >> 7;
            xs[kk * 34 + bb] = x[bb * 65536 + kbase + t + kk];
        }
        __syncthreads();
        const float* wrow = w + (size_t)(kbase + t) * 1024 + n0;
#pragma unroll 4
        for (int kk = 0; kk < 128; kk++) {
            float2 wv = *(const float2*)(wrow + (size_t)kk * 1024);
            float2 w0; w0.x = wv.x; w0.y = wv.x;
            float2 w1; w1.x = wv.y; w1.y = wv.y;
            const float2* xp = (const float2*)(xs + kk * 34);
#pragma unroll
            for (int bb = 0; bb < 16; bb++) {
                float2 xv = xp[bb];     // {batch 2bb, batch 2bb+1}
                a0[bb] = ffma2(xv, w0, a0[bb]);
                a1[bb] = ffma2(xv, w1, a1[bb]);
            }
        }
    }
    float* p = g_part + (size_t)blockIdx.y * 32 * 1024;
#pragma unroll
    for (int bb = 0; bb < 16; bb++) {
        p[(2 * bb) * 1024 + n0]         = a0[bb].x;
        p[(2 * bb + 1) * 1024 + n0]     = a0[bb].y;
        p[(2 * bb) * 1024 + n0 + 1]     = a1[bb].x;
        p[(2 * bb + 1) * 1024 + n0 + 1] = a1[bb].y;
    }
}

// ---------------- K7: reduce partials + bias + relu --------------------------
__global__ void k_dense1_fin(const float* __restrict__ bias) {
    int idx = blockIdx.x * 256 + threadIdx.x;   // 32*1024
    int n = idx & 1023, b = idx >> 10;
    float s = 0.f;
#pragma unroll 8
    for (int ks = 0; ks < 128; ks++) s += g_part[(ks * 32 + b) * 1024 + n];
    g_hidden[idx] = fmaxf(s + bias[n], 0.f);
}

// ---------------- K8: dense2 -> logits ---------------------------------------
__global__ void k_dense2(const float* __restrict__ w,
                         const float* __restrict__ bias,
                         float* __restrict__ logits) {
    int t = threadIdx.x;
    if (t >= 320) return;
    int b = t / 10, j = t % 10;
    float s = bias[j];
    const float* h = g_hidden + b * 1024;
#pragma unroll 8
    for (int k = 0; k < 1024; k++)
        s = fmaf(h[k], w[k * 10 + j], s);
    logits[b * 10 + j] = s;
}

// ---------------- launcher ---------------------------------------------------
extern "C" void kernel_launch(void* const* d_in, const int* in_sizes, int n_in,
                              void* d_out, int out_size) {
    const float* inputs = (const float*)d_in[0];
    const int*   labels = (const int*)d_in[1];   // dtype resolved on-device
    const float* c1w = (const float*)d_in[2];
    const float* c1b = (const float*)d_in[3];
    const float* c2w = (const float*)d_in[4];
    const float* c2b = (const float*)d_in[5];
    const float* d1w = (const float*)d_in[6];
    const float* d1b = (const float*)d_in[7];
    const float* d2w = (const float*)d_in[8];
    const float* d2b = (const float*)d_in[9];

    float* out = (float*)d_out;
    float* out_logits = out;                       // (32,10)
    float* out_pool   = out + 320;                 // (32,32,32,64)
    float* out_filt   = out + 320 + 2097152;       // (64,)

    static int smem_set = 0;
    if (!smem_set) {
        cudaFuncSetAttribute(k_conv2, cudaFuncAttributeMaxDynamicSharedMemorySize,
                             CONV2_SMEM);
        smem_set = 1;
    }

    k_conv1_pool<<<16384, 256>>>(inputs, c1w, c1b);
    k_conv2<<<512, 256, CONV2_SMEM>>>(c2w, c2b);
    k_amax<<<32, 512>>>();
    k_maskpool<<<8192, 256>>>(out_pool);
    k_filters<<<1, 64>>>(labels, out_filt);
    k_dense1<<<dim3(2, 128), 256>>>(out_pool, d1w);
    k_dense1_fin<<<128, 256>>>(d1b);
    k_dense2<<<1, 320>>>(d2w, d2b, out_logits);
}